// round 4
// baseline (speedup 1.0000x reference)
#include <cuda_runtime.h>

#define N_USERS 100000
#define N_ITEMS 50000
#define N_TOTAL (N_USERS + N_ITEMS)
#define D 64
#define D4Q 16                 // float4 per row
#define HYPER_X 0.5f
#define MAX_NNZ 2000000
#define MAX_SAMPLED 32768
#define SCAN_BLK 1024
#define SCAN_NB ((N_TOTAL + SCAN_BLK - 1) / SCAN_BLK)   // 147

// Feature buffers (layer-0 read straight from the inputs)
__device__ float g_e1[N_TOTAL * D];
__device__ float g_e2[N_TOTAL * D];
__device__ float g_e3[N_TOTAL * D];

// CSR scratch
__device__ int  g_deg[N_TOTAL];
__device__ int  g_offs[N_TOTAL + 1];
__device__ int  g_cursor[N_TOTAL];
__device__ int  g_blocksum[SCAN_NB];
__device__ int2 g_csr[MAX_NNZ];          // {col, float_as_int(val)}

// sampled-row dedup for masked layer 3
__device__ int g_flag[N_TOTAL];
__device__ int g_rowlist[MAX_SAMPLED];
__device__ int g_rowcount;

// ---------------------------------------------------------------------------
// zero: deg, flag, rowcount
// ---------------------------------------------------------------------------
__global__ void zero_kernel() {
    int i = blockIdx.x * blockDim.x + threadIdx.x;
    if (i < N_TOTAL) { g_deg[i] = 0; g_flag[i] = 0; }
    if (i == 0) g_rowcount = 0;
}

// ---------------------------------------------------------------------------
// fused: mark sampled rows (dedup) + degree histogram
// ---------------------------------------------------------------------------
__global__ void mark_hist_kernel(const int* __restrict__ users,
                                 const int* __restrict__ items, int B,
                                 const int* __restrict__ row, int nnz) {
    int i = blockIdx.x * blockDim.x + threadIdx.x;
    if (i < B) {
        int u = users[i];
        if (atomicExch(&g_flag[u], 1) == 0) {
            int p = atomicAdd(&g_rowcount, 1);
            g_rowlist[p] = u;
        }
        int it = N_USERS + items[i];
        if (atomicExch(&g_flag[it], 1) == 0) {
            int p = atomicAdd(&g_rowcount, 1);
            g_rowlist[p] = it;
        }
    }
    if (i < nnz) atomicAdd(&g_deg[row[i]], 1);
}

// ---------------------------------------------------------------------------
// scans
// ---------------------------------------------------------------------------
__device__ __forceinline__ int block_exscan(int v, int* sh) {
    int lane = threadIdx.x & 31, wid = threadIdx.x >> 5;
    int incl = v;
    #pragma unroll
    for (int o = 1; o < 32; o <<= 1) {
        int n = __shfl_up_sync(0xffffffffu, incl, o);
        if (lane >= o) incl += n;
    }
    if (lane == 31) sh[wid] = incl;
    __syncthreads();
    if (wid == 0) {
        int w = sh[lane];
        #pragma unroll
        for (int o = 1; o < 32; o <<= 1) {
            int n = __shfl_up_sync(0xffffffffu, w, o);
            if (lane >= o) w += n;
        }
        sh[lane] = w;
    }
    __syncthreads();
    int warpoff = (wid > 0) ? sh[wid - 1] : 0;
    return warpoff + incl - v;
}

__global__ void scan_partial_kernel() {
    __shared__ int sh[32];
    int i = blockIdx.x * SCAN_BLK + threadIdx.x;
    int v = (i < N_TOTAL) ? g_deg[i] : 0;
    int ex = block_exscan(v, sh);
    if (threadIdx.x == SCAN_BLK - 1) g_blocksum[blockIdx.x] = ex + v;
}

__global__ void scan_final_kernel() {
    __shared__ int sh[32];
    __shared__ int base_sh;
    if (threadIdx.x == 0) base_sh = 0;
    __syncthreads();
    int t = threadIdx.x;
    if (t < blockIdx.x) atomicAdd(&base_sh, g_blocksum[t]);
    __syncthreads();
    int i = blockIdx.x * SCAN_BLK + t;
    int v = (i < N_TOTAL) ? g_deg[i] : 0;
    int ex = block_exscan(v, sh) + base_sh;
    if (i < N_TOTAL) {
        g_offs[i]   = ex;
        g_cursor[i] = ex;
        if (i == N_TOTAL - 1) g_offs[N_TOTAL] = ex + v;
    }
}

__global__ void fill_kernel(const int* __restrict__ row,
                            const int* __restrict__ col,
                            const float* __restrict__ val, int nnz) {
    int e = blockIdx.x * blockDim.x + threadIdx.x;
    if (e < nnz) {
        int pos = atomicAdd(&g_cursor[row[e]], 1);
        g_csr[pos] = make_int2(col[e], __float_as_int(val[e]));
    }
}

// ---------------------------------------------------------------------------
// SpMM core: 1 warp per row, 16 lanes per edge, float4 per lane.
// Each warp-wide LDG.128 gathers two edges' rows (512B).
// ---------------------------------------------------------------------------
#define FETCH_META(J)                                                     \
    int c_ = 0, vi_ = 0;                                                  \
    if (q == 0) { int2 t = g_csr[(J) + half]; c_ = t.x; vi_ = t.y; }      \
    c_  = __shfl_sync(0xffffffffu, c_,  lane & 16);                       \
    vi_ = __shfl_sync(0xffffffffu, vi_, lane & 16);

__device__ __forceinline__ void spmm_row_body(
        int r, int lane, int half, int q,
        const float4* __restrict__ x, float4* __restrict__ y) {
    const int beg = __ldg(&g_offs[r]);
    const int end = __ldg(&g_offs[r + 1]);
    float4 acc = make_float4(0.f, 0.f, 0.f, 0.f);
    int j = beg;
    for (; j + 3 < end; j += 4) {
        int cA = 0, viA = 0, cB = 0, viB = 0;
        if (q == 0) {
            int2 tA = g_csr[j + half];     cA = tA.x; viA = tA.y;
            int2 tB = g_csr[j + 2 + half]; cB = tB.x; viB = tB.y;
        }
        cA  = __shfl_sync(0xffffffffu, cA,  lane & 16);
        viA = __shfl_sync(0xffffffffu, viA, lane & 16);
        cB  = __shfl_sync(0xffffffffu, cB,  lane & 16);
        viB = __shfl_sync(0xffffffffu, viB, lane & 16);
        float4 xA = __ldg(&x[(long)cA * D4Q + q]);
        float4 xB = __ldg(&x[(long)cB * D4Q + q]);
        float vA = __int_as_float(viA);
        float vB = __int_as_float(viB);
        acc.x += vA * xA.x; acc.y += vA * xA.y;
        acc.z += vA * xA.z; acc.w += vA * xA.w;
        acc.x += vB * xB.x; acc.y += vB * xB.y;
        acc.z += vB * xB.z; acc.w += vB * xB.w;
    }
    for (; j + 1 < end; j += 2) {
        FETCH_META(j)
        float4 xv = __ldg(&x[(long)c_ * D4Q + q]);
        float v = __int_as_float(vi_);
        acc.x += v * xv.x; acc.y += v * xv.y;
        acc.z += v * xv.z; acc.w += v * xv.w;
    }
    if (j < end) {   // tail edge: half 0 contributes, half 1 adds zero
        int c_ = 0, vi_ = 0;
        if (lane == 0) { int2 t = g_csr[j]; c_ = t.x; vi_ = t.y; }
        c_  = __shfl_sync(0xffffffffu, c_, 0);
        vi_ = __shfl_sync(0xffffffffu, vi_, 0);
        float v = (half == 0) ? __int_as_float(vi_) : 0.f;
        float4 xv = __ldg(&x[(long)c_ * D4Q + q]);
        acc.x += v * xv.x; acc.y += v * xv.y;
        acc.z += v * xv.z; acc.w += v * xv.w;
    }
    // combine halves
    acc.x += __shfl_xor_sync(0xffffffffu, acc.x, 16);
    acc.y += __shfl_xor_sync(0xffffffffu, acc.y, 16);
    acc.z += __shfl_xor_sync(0xffffffffu, acc.z, 16);
    acc.w += __shfl_xor_sync(0xffffffffu, acc.w, 16);
    if (half == 0) y[(long)r * D4Q + q] = acc;
}

__global__ void spmm_csr_kernel(const float4* __restrict__ x,
                                float4* __restrict__ y) {
    const int lane = threadIdx.x & 31;
    const int r = (blockIdx.x * blockDim.x + threadIdx.x) >> 5;
    if (r >= N_TOTAL) return;
    spmm_row_body(r, lane, lane >> 4, lane & 15, x, y);
}

// layer 1: gather from embedding inputs directly (pointer select per edge)
__global__ void spmm_l1_kernel(const float4* __restrict__ eu,
                               const float4* __restrict__ ei,
                               float4* __restrict__ y) {
    const int lane = threadIdx.x & 31;
    const int half = lane >> 4;
    const int q    = lane & 15;
    const int r = (blockIdx.x * blockDim.x + threadIdx.x) >> 5;
    if (r >= N_TOTAL) return;

    const int beg = __ldg(&g_offs[r]);
    const int end = __ldg(&g_offs[r + 1]);
    float4 acc = make_float4(0.f, 0.f, 0.f, 0.f);
    int j = beg;
    for (; j + 3 < end; j += 4) {
        int cA = 0, viA = 0, cB = 0, viB = 0;
        if (q == 0) {
            int2 tA = g_csr[j + half];     cA = tA.x; viA = tA.y;
            int2 tB = g_csr[j + 2 + half]; cB = tB.x; viB = tB.y;
        }
        cA  = __shfl_sync(0xffffffffu, cA,  lane & 16);
        viA = __shfl_sync(0xffffffffu, viA, lane & 16);
        cB  = __shfl_sync(0xffffffffu, cB,  lane & 16);
        viB = __shfl_sync(0xffffffffu, viB, lane & 16);
        const float4* bA = (cA < N_USERS) ? (eu + (long)cA * D4Q)
                                          : (ei + (long)(cA - N_USERS) * D4Q);
        const float4* bB = (cB < N_USERS) ? (eu + (long)cB * D4Q)
                                          : (ei + (long)(cB - N_USERS) * D4Q);
        float4 xA = __ldg(&bA[q]);
        float4 xB = __ldg(&bB[q]);
        float vA = __int_as_float(viA);
        float vB = __int_as_float(viB);
        acc.x += vA * xA.x; acc.y += vA * xA.y;
        acc.z += vA * xA.z; acc.w += vA * xA.w;
        acc.x += vB * xB.x; acc.y += vB * xB.y;
        acc.z += vB * xB.z; acc.w += vB * xB.w;
    }
    for (; j + 1 < end; j += 2) {
        FETCH_META(j)
        const float4* b = (c_ < N_USERS) ? (eu + (long)c_ * D4Q)
                                         : (ei + (long)(c_ - N_USERS) * D4Q);
        float4 xv = __ldg(&b[q]);
        float v = __int_as_float(vi_);
        acc.x += v * xv.x; acc.y += v * xv.y;
        acc.z += v * xv.z; acc.w += v * xv.w;
    }
    if (j < end) {
        int c_ = 0, vi_ = 0;
        if (lane == 0) { int2 t = g_csr[j]; c_ = t.x; vi_ = t.y; }
        c_  = __shfl_sync(0xffffffffu, c_, 0);
        vi_ = __shfl_sync(0xffffffffu, vi_, 0);
        const float4* b = (c_ < N_USERS) ? (eu + (long)c_ * D4Q)
                                         : (ei + (long)(c_ - N_USERS) * D4Q);
        float v = (half == 0) ? __int_as_float(vi_) : 0.f;
        float4 xv = __ldg(&b[q]);
        acc.x += v * xv.x; acc.y += v * xv.y;
        acc.z += v * xv.z; acc.w += v * xv.w;
    }
    acc.x += __shfl_xor_sync(0xffffffffu, acc.x, 16);
    acc.y += __shfl_xor_sync(0xffffffffu, acc.y, 16);
    acc.z += __shfl_xor_sync(0xffffffffu, acc.z, 16);
    acc.w += __shfl_xor_sync(0xffffffffu, acc.w, 16);
    if (half == 0) y[(long)r * D4Q + q] = acc;
}

// layer 3: only sampled rows
__global__ void spmm_list_kernel(const float4* __restrict__ x,
                                 float4* __restrict__ y) {
    const int lane = threadIdx.x & 31;
    const int idx = (blockIdx.x * blockDim.x + threadIdx.x) >> 5;
    if (idx >= g_rowcount) return;
    const int r = g_rowlist[idx];
    spmm_row_body(r, lane, lane >> 4, lane & 15, x, y);
}

// ---------------------------------------------------------------------------
// Epilogue
// ---------------------------------------------------------------------------
#define SAMPLES_PER_BLOCK 8

__device__ __forceinline__ float sigmoidf_(float x) {
    return 1.0f / (1.0f + expf(-x));
}

__global__ void epilogue_kernel(const float* __restrict__ emb_user,
                                const float* __restrict__ emb_item,
                                const float* __restrict__ w_user,
                                const float* __restrict__ w_item,
                                const float* __restrict__ xij_emb1,
                                const float* __restrict__ xij_emb0,
                                const int* __restrict__ users,
                                const int* __restrict__ items,
                                const int* __restrict__ xij,
                                float* __restrict__ out,
                                int B) {
    __shared__ float ws_u[D * D];                 // transposed
    __shared__ float ws_i[D * D];
    __shared__ float su[SAMPLES_PER_BLOCK][D];
    __shared__ float si[SAMPLES_PER_BLOCK][D];

    const int tid = threadIdx.x;
    for (int idx = tid; idx < D * D; idx += blockDim.x) {
        int d = idx >> 6, k = idx & 63;
        ws_u[k * D + d] = w_user[idx];
        ws_i[k * D + d] = w_item[idx];
    }

    const int w    = tid >> 5;
    const int lane = tid & 31;
    const int s    = blockIdx.x * SAMPLES_PER_BLOCK + w;

    int item = 0;
    if (s < B) {
        int urow = users[s];
        item = items[s];
        int irow = N_USERS + item;
        #pragma unroll
        for (int t = 0; t < 2; t++) {
            int j = lane + t * 32;
            long uo = (long)urow * D + j;
            long io = (long)irow * D + j;
            su[w][j] = 0.25f * (emb_user[uo] + g_e1[uo] + g_e2[uo] + g_e3[uo]);
            si[w][j] = 0.25f * (emb_item[(long)item * D + j]
                                + g_e1[io] + g_e2[io] + g_e3[io]);
        }
    }
    __syncthreads();
    if (s >= B) return;

    float au0 = 0.f, au1 = 0.f, ai0 = 0.f, ai1 = 0.f;
    #pragma unroll
    for (int k = 0; k < D; k++) {
        float uk = su[w][k];
        float ik = si[w][k];
        au0 += ws_u[k * D + lane]      * uk;
        au1 += ws_u[k * D + lane + 32] * uk;
        ai0 += ws_i[k * D + lane]      * ik;
        ai1 += ws_i[k * D + lane + 32] * ik;
    }

    float m = fmaxf(au0, au1);
    #pragma unroll
    for (int off = 16; off > 0; off >>= 1)
        m = fmaxf(m, __shfl_xor_sync(0xffffffffu, m, off));
    float ex0 = expf(au0 - m);
    float ex1 = expf(au1 - m);
    float ssum = ex0 + ex1;
    float tdot = ex0 * sigmoidf_(ai0) + ex1 * sigmoidf_(ai1);
    #pragma unroll
    for (int off = 16; off > 0; off >>= 1) {
        ssum += __shfl_xor_sync(0xffffffffu, ssum, off);
        tdot += __shfl_xor_sync(0xffffffffu, tdot, off);
    }

    if (lane == 0) {
        float xe = (xij[s] > 0) ? xij_emb1[item] : xij_emb0[item];
        out[s] = (1.0f - HYPER_X) * (tdot / ssum) + HYPER_X * sigmoidf_(xe);
    }
}

// ---------------------------------------------------------------------------
// kernel_launch
// ---------------------------------------------------------------------------
extern "C" void kernel_launch(void* const* d_in, const int* in_sizes, int n_in,
                              void* d_out, int out_size) {
    const float* emb_user = (const float*)d_in[0];
    const float* emb_item = (const float*)d_in[1];
    const float* w_user   = (const float*)d_in[2];
    const float* w_item   = (const float*)d_in[3];
    const float* xij_emb1 = (const float*)d_in[4];
    const float* xij_emb0 = (const float*)d_in[5];
    const float* g_val    = (const float*)d_in[6];
    const int*   g_row    = (const int*)d_in[7];
    const int*   g_col    = (const int*)d_in[8];
    const int*   users    = (const int*)d_in[9];
    const int*   items    = (const int*)d_in[10];
    const int*   xij      = (const int*)d_in[11];
    float*       out      = (float*)d_out;

    const int nnz = in_sizes[6];
    const int B   = in_sizes[9];

    float *e1, *e2, *e3;
    cudaGetSymbolAddress((void**)&e1, g_e1);
    cudaGetSymbolAddress((void**)&e2, g_e2);
    cudaGetSymbolAddress((void**)&e3, g_e3);

    zero_kernel<<<(N_TOTAL + 255) / 256, 256>>>();
    mark_hist_kernel<<<(nnz + 255) / 256, 256>>>(users, items, B, g_row, nnz);
    scan_partial_kernel<<<SCAN_NB, SCAN_BLK>>>();
    scan_final_kernel<<<SCAN_NB, SCAN_BLK>>>();
    fill_kernel<<<(nnz + 255) / 256, 256>>>(g_row, g_col, g_val, nnz);

    const int warps_per_block = 8;                 // 256 threads
    const int sblocks = (N_TOTAL + warps_per_block - 1) / warps_per_block;
    spmm_l1_kernel<<<sblocks, 256>>>((const float4*)emb_user,
                                     (const float4*)emb_item, (float4*)e1);
    spmm_csr_kernel<<<sblocks, 256>>>((const float4*)e1, (float4*)e2);
    const int lblocks = (MAX_SAMPLED + warps_per_block - 1) / warps_per_block;
    spmm_list_kernel<<<lblocks, 256>>>((const float4*)e2, (float4*)e3);

    const int eblocks = (B + SAMPLES_PER_BLOCK - 1) / SAMPLES_PER_BLOCK;
    epilogue_kernel<<<eblocks, 256>>>(emb_user, emb_item, w_user, w_item,
                                      xij_emb1, xij_emb0, users, items, xij,
                                      out, B);
}

// round 5
// speedup vs baseline: 1.0369x; 1.0369x over previous
#include <cuda_runtime.h>

#define N_USERS 100000
#define N_ITEMS 50000
#define N_TOTAL (N_USERS + N_ITEMS)
#define D 64
#define D2 (D / 2)
#define HYPER_X 0.5f
#define MAX_NNZ 2000000
#define MAX_SAMPLED 32768
#define SCAN_BLK 1024
#define SCAN_NB ((N_TOTAL + SCAN_BLK - 1) / SCAN_BLK)   // 147

// Feature buffers (layer-0 read straight from the inputs)
__device__ float g_e1[N_TOTAL * D];
__device__ float g_e2[N_TOTAL * D];
__device__ float g_e3[N_TOTAL * D];

// CSR scratch
__device__ int  g_deg[N_TOTAL];
__device__ int  g_offs[N_TOTAL + 1];
__device__ int  g_cursor[N_TOTAL];
__device__ int  g_blocksum[SCAN_NB];
__device__ int2 g_csr[MAX_NNZ];          // {col, float_as_int(val)}

// sampled-row dedup for masked layer 3
__device__ int g_flag[N_TOTAL];
__device__ int g_rowlist[MAX_SAMPLED];
__device__ int g_rowcount;

// ---------------------------------------------------------------------------
// zero: deg, flag, rowcount
// ---------------------------------------------------------------------------
__global__ void zero_kernel() {
    int i = blockIdx.x * blockDim.x + threadIdx.x;
    if (i < N_TOTAL) { g_deg[i] = 0; g_flag[i] = 0; }
    if (i == 0) g_rowcount = 0;
}

// ---------------------------------------------------------------------------
// fused: mark sampled rows (dedup) + degree histogram
// ---------------------------------------------------------------------------
__global__ void mark_hist_kernel(const int* __restrict__ users,
                                 const int* __restrict__ items, int B,
                                 const int* __restrict__ row, int nnz) {
    int i = blockIdx.x * blockDim.x + threadIdx.x;
    if (i < B) {
        int u = users[i];
        if (atomicExch(&g_flag[u], 1) == 0) {
            int p = atomicAdd(&g_rowcount, 1);
            g_rowlist[p] = u;
        }
        int it = N_USERS + items[i];
        if (atomicExch(&g_flag[it], 1) == 0) {
            int p = atomicAdd(&g_rowcount, 1);
            g_rowlist[p] = it;
        }
    }
    if (i < nnz) atomicAdd(&g_deg[row[i]], 1);
}

// ---------------------------------------------------------------------------
// scans
// ---------------------------------------------------------------------------
__device__ __forceinline__ int block_exscan(int v, int* sh) {
    int lane = threadIdx.x & 31, wid = threadIdx.x >> 5;
    int incl = v;
    #pragma unroll
    for (int o = 1; o < 32; o <<= 1) {
        int n = __shfl_up_sync(0xffffffffu, incl, o);
        if (lane >= o) incl += n;
    }
    if (lane == 31) sh[wid] = incl;
    __syncthreads();
    if (wid == 0) {
        int w = sh[lane];
        #pragma unroll
        for (int o = 1; o < 32; o <<= 1) {
            int n = __shfl_up_sync(0xffffffffu, w, o);
            if (lane >= o) w += n;
        }
        sh[lane] = w;
    }
    __syncthreads();
    int warpoff = (wid > 0) ? sh[wid - 1] : 0;
    return warpoff + incl - v;
}

__global__ void scan_partial_kernel() {
    __shared__ int sh[32];
    int i = blockIdx.x * SCAN_BLK + threadIdx.x;
    int v = (i < N_TOTAL) ? g_deg[i] : 0;
    int ex = block_exscan(v, sh);
    if (threadIdx.x == SCAN_BLK - 1) g_blocksum[blockIdx.x] = ex + v;
}

__global__ void scan_final_kernel() {
    __shared__ int sh[32];
    __shared__ int base_sh;
    if (threadIdx.x == 0) base_sh = 0;
    __syncthreads();
    int t = threadIdx.x;
    if (t < blockIdx.x) atomicAdd(&base_sh, g_blocksum[t]);
    __syncthreads();
    int i = blockIdx.x * SCAN_BLK + t;
    int v = (i < N_TOTAL) ? g_deg[i] : 0;
    int ex = block_exscan(v, sh) + base_sh;
    if (i < N_TOTAL) {
        g_offs[i]   = ex;
        g_cursor[i] = ex;
        if (i == N_TOTAL - 1) g_offs[N_TOTAL] = ex + v;
    }
}

__global__ void fill_kernel(const int* __restrict__ row,
                            const int* __restrict__ col,
                            const float* __restrict__ val, int nnz) {
    int e = blockIdx.x * blockDim.x + threadIdx.x;
    if (e < nnz) {
        int pos = atomicAdd(&g_cursor[row[e]], 1);
        g_csr[pos] = make_int2(col[e], __float_as_int(val[e]));
    }
}

// ---------------------------------------------------------------------------
// SpMM: 1 warp per row, float2 per lane (32 lanes cover the 64-dim row).
// Metadata g_csr[j] loaded uniformly by all lanes (broadcast LDG).
// Unroll x4 for MLP ~8 (4 gathers + 4 metadata loads in flight).
// ---------------------------------------------------------------------------
__device__ __forceinline__ void spmm_row_float2(
        int r, int lane,
        const float2* __restrict__ x, float2* __restrict__ y) {
    const int beg = __ldg(&g_offs[r]);
    const int end = __ldg(&g_offs[r + 1]);

    float ax = 0.f, ay = 0.f;
    int j = beg;
    for (; j + 3 < end; j += 4) {
        int2 m0 = __ldg(&g_csr[j]);
        int2 m1 = __ldg(&g_csr[j + 1]);
        int2 m2 = __ldg(&g_csr[j + 2]);
        int2 m3 = __ldg(&g_csr[j + 3]);
        float2 x0 = __ldg(&x[(long)m0.x * D2 + lane]);
        float2 x1 = __ldg(&x[(long)m1.x * D2 + lane]);
        float2 x2 = __ldg(&x[(long)m2.x * D2 + lane]);
        float2 x3 = __ldg(&x[(long)m3.x * D2 + lane]);
        float v0 = __int_as_float(m0.y);
        float v1 = __int_as_float(m1.y);
        float v2 = __int_as_float(m2.y);
        float v3 = __int_as_float(m3.y);
        ax += v0 * x0.x; ay += v0 * x0.y;
        ax += v1 * x1.x; ay += v1 * x1.y;
        ax += v2 * x2.x; ay += v2 * x2.y;
        ax += v3 * x3.x; ay += v3 * x3.y;
    }
    for (; j < end; j++) {
        int2 m = __ldg(&g_csr[j]);
        float2 xv = __ldg(&x[(long)m.x * D2 + lane]);
        float v = __int_as_float(m.y);
        ax += v * xv.x; ay += v * xv.y;
    }
    y[(long)r * D2 + lane] = make_float2(ax, ay);
}

__global__ void spmm_csr_kernel(const float2* __restrict__ x,
                                float2* __restrict__ y) {
    const int lane = threadIdx.x & 31;
    const int r = (blockIdx.x * blockDim.x + threadIdx.x) >> 5;
    if (r >= N_TOTAL) return;
    spmm_row_float2(r, lane, x, y);
}

// layer 1: gather straight from embedding inputs (pointer select per edge)
__global__ void spmm_l1_kernel(const float2* __restrict__ eu,
                               const float2* __restrict__ ei,
                               float2* __restrict__ y) {
    const int lane = threadIdx.x & 31;
    const int r = (blockIdx.x * blockDim.x + threadIdx.x) >> 5;
    if (r >= N_TOTAL) return;

    const int beg = __ldg(&g_offs[r]);
    const int end = __ldg(&g_offs[r + 1]);

    float ax = 0.f, ay = 0.f;
    int j = beg;
    for (; j + 3 < end; j += 4) {
        int2 m0 = __ldg(&g_csr[j]);
        int2 m1 = __ldg(&g_csr[j + 1]);
        int2 m2 = __ldg(&g_csr[j + 2]);
        int2 m3 = __ldg(&g_csr[j + 3]);
        const float2* b0 = (m0.x < N_USERS) ? (eu + (long)m0.x * D2)
                                            : (ei + (long)(m0.x - N_USERS) * D2);
        const float2* b1 = (m1.x < N_USERS) ? (eu + (long)m1.x * D2)
                                            : (ei + (long)(m1.x - N_USERS) * D2);
        const float2* b2 = (m2.x < N_USERS) ? (eu + (long)m2.x * D2)
                                            : (ei + (long)(m2.x - N_USERS) * D2);
        const float2* b3 = (m3.x < N_USERS) ? (eu + (long)m3.x * D2)
                                            : (ei + (long)(m3.x - N_USERS) * D2);
        float2 x0 = __ldg(&b0[lane]);
        float2 x1 = __ldg(&b1[lane]);
        float2 x2 = __ldg(&b2[lane]);
        float2 x3 = __ldg(&b3[lane]);
        float v0 = __int_as_float(m0.y);
        float v1 = __int_as_float(m1.y);
        float v2 = __int_as_float(m2.y);
        float v3 = __int_as_float(m3.y);
        ax += v0 * x0.x; ay += v0 * x0.y;
        ax += v1 * x1.x; ay += v1 * x1.y;
        ax += v2 * x2.x; ay += v2 * x2.y;
        ax += v3 * x3.x; ay += v3 * x3.y;
    }
    for (; j < end; j++) {
        int2 m = __ldg(&g_csr[j]);
        const float2* b = (m.x < N_USERS) ? (eu + (long)m.x * D2)
                                          : (ei + (long)(m.x - N_USERS) * D2);
        float2 xv = __ldg(&b[lane]);
        float v = __int_as_float(m.y);
        ax += v * xv.x; ay += v * xv.y;
    }
    y[(long)r * D2 + lane] = make_float2(ax, ay);
}

// layer 3: only sampled rows
__global__ void spmm_list_kernel(const float2* __restrict__ x,
                                 float2* __restrict__ y) {
    const int lane = threadIdx.x & 31;
    const int idx = (blockIdx.x * blockDim.x + threadIdx.x) >> 5;
    if (idx >= g_rowcount) return;
    const int r = g_rowlist[idx];
    spmm_row_float2(r, lane, x, y);
}

// ---------------------------------------------------------------------------
// Epilogue
// ---------------------------------------------------------------------------
#define SAMPLES_PER_BLOCK 8

__device__ __forceinline__ float sigmoidf_(float x) {
    return 1.0f / (1.0f + expf(-x));
}

__global__ void epilogue_kernel(const float* __restrict__ emb_user,
                                const float* __restrict__ emb_item,
                                const float* __restrict__ w_user,
                                const float* __restrict__ w_item,
                                const float* __restrict__ xij_emb1,
                                const float* __restrict__ xij_emb0,
                                const int* __restrict__ users,
                                const int* __restrict__ items,
                                const int* __restrict__ xij,
                                float* __restrict__ out,
                                int B) {
    __shared__ float ws_u[D * D];                 // transposed
    __shared__ float ws_i[D * D];
    __shared__ float su[SAMPLES_PER_BLOCK][D];
    __shared__ float si[SAMPLES_PER_BLOCK][D];

    const int tid = threadIdx.x;
    for (int idx = tid; idx < D * D; idx += blockDim.x) {
        int d = idx >> 6, k = idx & 63;
        ws_u[k * D + d] = w_user[idx];
        ws_i[k * D + d] = w_item[idx];
    }

    const int w    = tid >> 5;
    const int lane = tid & 31;
    const int s    = blockIdx.x * SAMPLES_PER_BLOCK + w;

    int item = 0;
    if (s < B) {
        int urow = users[s];
        item = items[s];
        int irow = N_USERS + item;
        #pragma unroll
        for (int t = 0; t < 2; t++) {
            int j = lane + t * 32;
            long uo = (long)urow * D + j;
            long io = (long)irow * D + j;
            su[w][j] = 0.25f * (emb_user[uo] + g_e1[uo] + g_e2[uo] + g_e3[uo]);
            si[w][j] = 0.25f * (emb_item[(long)item * D + j]
                                + g_e1[io] + g_e2[io] + g_e3[io]);
        }
    }
    __syncthreads();
    if (s >= B) return;

    float au0 = 0.f, au1 = 0.f, ai0 = 0.f, ai1 = 0.f;
    #pragma unroll
    for (int k = 0; k < D; k++) {
        float uk = su[w][k];
        float ik = si[w][k];
        au0 += ws_u[k * D + lane]      * uk;
        au1 += ws_u[k * D + lane + 32] * uk;
        ai0 += ws_i[k * D + lane]      * ik;
        ai1 += ws_i[k * D + lane + 32] * ik;
    }

    float m = fmaxf(au0, au1);
    #pragma unroll
    for (int off = 16; off > 0; off >>= 1)
        m = fmaxf(m, __shfl_xor_sync(0xffffffffu, m, off));
    float ex0 = expf(au0 - m);
    float ex1 = expf(au1 - m);
    float ssum = ex0 + ex1;
    float tdot = ex0 * sigmoidf_(ai0) + ex1 * sigmoidf_(ai1);
    #pragma unroll
    for (int off = 16; off > 0; off >>= 1) {
        ssum += __shfl_xor_sync(0xffffffffu, ssum, off);
        tdot += __shfl_xor_sync(0xffffffffu, tdot, off);
    }

    if (lane == 0) {
        float xe = (xij[s] > 0) ? xij_emb1[item] : xij_emb0[item];
        out[s] = (1.0f - HYPER_X) * (tdot / ssum) + HYPER_X * sigmoidf_(xe);
    }
}

// ---------------------------------------------------------------------------
// kernel_launch
// ---------------------------------------------------------------------------
extern "C" void kernel_launch(void* const* d_in, const int* in_sizes, int n_in,
                              void* d_out, int out_size) {
    const float* emb_user = (const float*)d_in[0];
    const float* emb_item = (const float*)d_in[1];
    const float* w_user   = (const float*)d_in[2];
    const float* w_item   = (const float*)d_in[3];
    const float* xij_emb1 = (const float*)d_in[4];
    const float* xij_emb0 = (const float*)d_in[5];
    const float* g_val    = (const float*)d_in[6];
    const int*   g_row    = (const int*)d_in[7];
    const int*   g_col    = (const int*)d_in[8];
    const int*   users    = (const int*)d_in[9];
    const int*   items    = (const int*)d_in[10];
    const int*   xij      = (const int*)d_in[11];
    float*       out      = (float*)d_out;

    const int nnz = in_sizes[6];
    const int B   = in_sizes[9];

    float *e1, *e2, *e3;
    cudaGetSymbolAddress((void**)&e1, g_e1);
    cudaGetSymbolAddress((void**)&e2, g_e2);
    cudaGetSymbolAddress((void**)&e3, g_e3);

    zero_kernel<<<(N_TOTAL + 255) / 256, 256>>>();
    mark_hist_kernel<<<(nnz + 255) / 256, 256>>>(users, items, B, g_row, nnz);
    scan_partial_kernel<<<SCAN_NB, SCAN_BLK>>>();
    scan_final_kernel<<<SCAN_NB, SCAN_BLK>>>();
    fill_kernel<<<(nnz + 255) / 256, 256>>>(g_row, g_col, g_val, nnz);

    const int warps_per_block = 8;                 // 256 threads
    const int sblocks = (N_TOTAL + warps_per_block - 1) / warps_per_block;
    spmm_l1_kernel<<<sblocks, 256>>>((const float2*)emb_user,
                                     (const float2*)emb_item, (float2*)e1);
    spmm_csr_kernel<<<sblocks, 256>>>((const float2*)e1, (float2*)e2);
    const int lblocks = (MAX_SAMPLED + warps_per_block - 1) / warps_per_block;
    spmm_list_kernel<<<lblocks, 256>>>((const float2*)e2, (float2*)e3);

    const int eblocks = (B + SAMPLES_PER_BLOCK - 1) / SAMPLES_PER_BLOCK;
    epilogue_kernel<<<eblocks, 256>>>(emb_user, emb_item, w_user, w_item,
                                      xij_emb1, xij_emb0, users, items, xij,
                                      out, B);
}